// round 1
// baseline (speedup 1.0000x reference)
#include <cuda_runtime.h>

#define NB   16
#define CIN  512
#define COUT 512
#define HID  512
#define HH   64
#define WW   64
#define KTAPS 9
#define KTOT (CIN*KTAPS)   // 4608

// Static device scratch (no runtime allocation allowed)
__device__ float g_s[NB*CIN];          // style scales s[b,i]
__device__ float g_d[NB*COUT];         // demod coeffs d[b,o]
__device__ float g_wt[KTOT*COUT];      // K-major scaled weights: [(i*9+t)*COUT + o]
__device__ float g_w2[CIN*COUT];       // sum_t w^2 : [i*COUT + o]

// ---------------------------------------------------------------------------
// Prep 1: re-lay weights K-major, scale by runtime_coef, accumulate squares
// grid = CIN blocks, COUT threads
__global__ void prep_wt(const float* __restrict__ weight) {
    const int i = blockIdx.x;
    const int o = threadIdx.x;
    const float coef = rsqrtf((float)(CIN * KTAPS));
    const float* wsrc = weight + ((size_t)o * CIN + i) * KTAPS;
    float sum = 0.f;
#pragma unroll
    for (int t = 0; t < KTAPS; ++t) {
        float v = wsrc[t] * coef;
        g_wt[(i * KTAPS + t) * COUT + o] = v;
        sum += v * v;
    }
    g_w2[i * COUT + o] = sum;
}

// ---------------------------------------------------------------------------
// Prep 2: style modulation s[b,i] = (y[b,:] . mod_w[i,:]) / sqrt(HID) + mod_b[i] + 1
// grid = NB blocks, CIN threads
__global__ void prep_s(const float* __restrict__ y,
                       const float* __restrict__ mod_w,
                       const float* __restrict__ mod_b) {
    const int b = blockIdx.x;
    const int i = threadIdx.x;
    const float ms = rsqrtf((float)HID);
    const float4* yr = (const float4*)(y + (size_t)b * HID);
    const float4* wr = (const float4*)(mod_w + (size_t)i * HID);
    float acc = 0.f;
#pragma unroll 8
    for (int h = 0; h < HID / 4; ++h) {
        float4 a = yr[h];
        float4 w = wr[h];
        acc += a.x * w.x + a.y * w.y + a.z * w.z + a.w * w.w;
    }
    g_s[b * CIN + i] = acc * ms + mod_b[i] + 1.0f;
}

// ---------------------------------------------------------------------------
// Prep 3: demod d[b,o] = rsqrt( sum_i w2[i,o] * s[b,i]^2 + 1e-8 )
// grid = NB blocks, COUT threads
__global__ void prep_d() {
    const int b = blockIdx.x;
    const int o = threadIdx.x;
    __shared__ float s2[CIN];
    for (int i = threadIdx.x; i < CIN; i += blockDim.x) {
        float s = g_s[b * CIN + i];
        s2[i] = s * s;
    }
    __syncthreads();
    float acc = 0.f;
#pragma unroll 8
    for (int i = 0; i < CIN; ++i)
        acc += g_w2[i * COUT + o] * s2[i];
    g_d[b * COUT + o] = rsqrtf(acc + 1e-8f);
}

// ---------------------------------------------------------------------------
// Main implicit-GEMM conv:
//   out[b,o,h,w] = d[b,o] * sum_{i,t} wt[i,t,o] * s[b,i] * x[b,i,h+dy-1,w+dx-1]
//                  + noise[b,h,w]*noise_scale + bias[o]
// Block tile: M=128 (cout) x N=128 (2 rows x 64 cols). K-step: one channel (9 taps).
// 256 threads, per-thread 8x8 microtile.
__global__ __launch_bounds__(256, 2)
void conv_main(const float* __restrict__ x,
               const float* __restrict__ noise,
               const float* __restrict__ bias,
               const float* __restrict__ noise_scale,
               float* __restrict__ out) {
    __shared__ __align__(16) float As[KTAPS][128];
    __shared__ __align__(16) float Bs[KTAPS][128];

    const int b  = blockIdx.z;
    const int o0 = blockIdx.y * 128;
    const int h0 = blockIdx.x * 2;
    const int tid = threadIdx.x;
    const int tm = tid >> 4;   // 0..15
    const int tn = tid & 15;   // 0..15

    float acc[8][8];
#pragma unroll
    for (int mi = 0; mi < 8; ++mi)
#pragma unroll
        for (int ni = 0; ni < 8; ++ni)
            acc[mi][ni] = 0.f;

    const float* xb = x + (size_t)b * CIN * HH * WW;
    const float* sb = g_s + b * CIN;

    for (int i = 0; i < CIN; ++i) {
        const float s_bi = sb[i];
        const float* wtp = g_wt + (size_t)(i * KTAPS) * COUT + o0;
        const float* xp  = xb + (size_t)i * HH * WW;

        // fill: 9*128 = 1152 elements each for A and B
        for (int idx = tid; idx < KTAPS * 128; idx += 256) {
            const int t = idx >> 7;       // 0..8
            const int n = idx & 127;
            As[t][n] = wtp[t * COUT + n];
            const int dy = t / 3;
            const int dx = t - dy * 3;
            const int h = h0 + (n >> 6) + dy - 1;
            const int w = (n & 63) + dx - 1;
            float v = 0.f;
            if (((unsigned)h < HH) & ((unsigned)w < WW))
                v = xp[h * WW + w];
            Bs[t][n] = v * s_bi;
        }
        __syncthreads();

#pragma unroll
        for (int t = 0; t < KTAPS; ++t) {
            const float4 a0 = *(const float4*)(&As[t][tm * 4]);
            const float4 a1 = *(const float4*)(&As[t][tm * 4 + 64]);
            const float4 b0 = *(const float4*)(&Bs[t][tn * 4]);
            const float4 b1 = *(const float4*)(&Bs[t][tn * 4 + 64]);
            const float av[8] = {a0.x, a0.y, a0.z, a0.w, a1.x, a1.y, a1.z, a1.w};
            const float bv[8] = {b0.x, b0.y, b0.z, b0.w, b1.x, b1.y, b1.z, b1.w};
#pragma unroll
            for (int mi = 0; mi < 8; ++mi)
#pragma unroll
                for (int ni = 0; ni < 8; ++ni)
                    acc[mi][ni] = fmaf(av[mi], bv[ni], acc[mi][ni]);
        }
        __syncthreads();
    }

    // epilogue
    const float ns = noise_scale[0];
    const int c0 = tn * 4;
#pragma unroll
    for (int mi = 0; mi < 8; ++mi) {
        const int o = o0 + ((mi < 4) ? (tm * 4 + mi) : (64 + tm * 4 + (mi - 4)));
        const float dd = g_d[b * COUT + o];
        const float bv = bias[o];
#pragma unroll
        for (int r = 0; r < 2; ++r) {
            const int h = h0 + r;
            const float4 nz = *(const float4*)(noise + ((size_t)b * HH + h) * WW + c0);
            float4 res;
            res.x = acc[mi][r * 4 + 0] * dd + nz.x * ns + bv;
            res.y = acc[mi][r * 4 + 1] * dd + nz.y * ns + bv;
            res.z = acc[mi][r * 4 + 2] * dd + nz.z * ns + bv;
            res.w = acc[mi][r * 4 + 3] * dd + nz.w * ns + bv;
            *(float4*)(out + (((size_t)b * COUT + o) * HH + h) * WW + c0) = res;
        }
    }
}

// ---------------------------------------------------------------------------
extern "C" void kernel_launch(void* const* d_in, const int* in_sizes, int n_in,
                              void* d_out, int out_size) {
    const float* x           = (const float*)d_in[0];
    const float* y           = (const float*)d_in[1];
    const float* noise       = (const float*)d_in[2];
    const float* weight      = (const float*)d_in[3];
    const float* bias        = (const float*)d_in[4];
    const float* mod_w       = (const float*)d_in[5];
    const float* mod_b       = (const float*)d_in[6];
    const float* noise_scale = (const float*)d_in[7];
    float* out = (float*)d_out;

    prep_wt<<<CIN, COUT>>>(weight);
    prep_s<<<NB, CIN>>>(y, mod_w, mod_b);
    prep_d<<<NB, COUT>>>();
    conv_main<<<dim3(HH / 2, COUT / 128, NB), 256>>>(x, noise, bias, noise_scale, out);
}

// round 3
// speedup vs baseline: 2.6620x; 2.6620x over previous
#include <cuda_runtime.h>
#include <cuda_bf16.h>
#include <cstdint>

#define NB   16
#define CIN  512
#define COUT 512
#define HID  512
#define HH   64
#define WW   64
#define KTAPS 9
#define KTOT 4608
#define NPIX 4096

#define KC     32                  // bf16 K per chunk
#define NCH    (KTOT / KC)         // 144
#define TILEB  (128 * KC * 2)      // 8192 B per tile
#define STAGEB (4 * TILEB)         // 32768 B
#define NSTAGE 3
#define DYN_SMEM (NSTAGE * STAGEB) // 96 KB

// ---------------- static device scratch -------------------------------------
__device__ float g_s[NB * CIN];
__device__ float g_d[NB * COUT];
__device__ float g_w2[CIN * COUT];                       // sum_t w^2, [i][o]
__device__ __nv_bfloat16 g_Wh[(size_t)COUT * KTOT];      // weights k-major hi
__device__ __nv_bfloat16 g_Wl[(size_t)COUT * KTOT];      // lo
__device__ __nv_bfloat16 g_xsh[(size_t)NB * NPIX * CIN]; // (x*s) [b][p][i] hi
__device__ __nv_bfloat16 g_xsl[(size_t)NB * NPIX * CIN]; // lo

// ---------------- helpers ----------------------------------------------------
__device__ __forceinline__ uint32_t s2u(const void* p) {
    uint32_t a;
    asm("{ .reg .u64 t; cvta.to.shared.u64 t, %1; cvt.u32.u64 %0, t; }" : "=r"(a) : "l"(p));
    return a;
}
__device__ __forceinline__ void cp_ca16(uint32_t dst, const void* src, int sz) {
    asm volatile("cp.async.ca.shared.global [%0], [%1], 16, %2;"
                 :: "r"(dst), "l"(src), "r"(sz) : "memory");
}
__device__ __forceinline__ void cp_cg16(uint32_t dst, const void* src, int sz) {
    asm volatile("cp.async.cg.shared.global [%0], [%1], 16, %2;"
                 :: "r"(dst), "l"(src), "r"(sz) : "memory");
}
__device__ __forceinline__ void cp_commit() {
    asm volatile("cp.async.commit_group;" ::: "memory");
}
__device__ __forceinline__ void cp_wait1() {
    asm volatile("cp.async.wait_group 1;" ::: "memory");
}
__device__ __forceinline__ void ldsm4(uint32_t* r, uint32_t addr) {
    asm volatile("ldmatrix.sync.aligned.m8n8.x4.shared.b16 {%0,%1,%2,%3}, [%4];"
                 : "=r"(r[0]), "=r"(r[1]), "=r"(r[2]), "=r"(r[3]) : "r"(addr));
}
#define MMA(c, a, B0, B1) \
    asm volatile("mma.sync.aligned.m16n8k16.row.col.f32.bf16.bf16.f32 " \
                 "{%0,%1,%2,%3},{%4,%5,%6,%7},{%8,%9},{%0,%1,%2,%3};" \
                 : "+f"((c)[0]), "+f"((c)[1]), "+f"((c)[2]), "+f"((c)[3]) \
                 : "r"((a)[0]), "r"((a)[1]), "r"((a)[2]), "r"((a)[3]), \
                   "r"(B0), "r"(B1))

// ---------------------------------------------------------------------------
// Prep 1: style s[b,i]
__global__ void prep_s(const float* __restrict__ y,
                       const float* __restrict__ mod_w,
                       const float* __restrict__ mod_b) {
    const int b = blockIdx.x;
    const int i = threadIdx.x;
    const float ms = rsqrtf((float)HID);
    const float4* yr = (const float4*)(y + (size_t)b * HID);
    const float4* wr = (const float4*)(mod_w + (size_t)i * HID);
    float acc = 0.f;
#pragma unroll 8
    for (int h = 0; h < HID / 4; ++h) {
        float4 a = yr[h];
        float4 w = wr[h];
        acc += a.x * w.x + a.y * w.y + a.z * w.z + a.w * w.w;
    }
    g_s[b * CIN + i] = acc * ms + mod_b[i] + 1.0f;
}

// ---------------------------------------------------------------------------
// Prep 2: scaled weights -> k-major hi/lo split (k = t*512 + i), plus g_w2[i][o]
__global__ void prep_w(const float* __restrict__ weight) {
    __shared__ float sm[KTOT];
    const int o = blockIdx.x;
    const int tid = threadIdx.x;
    const float coef = rsqrtf((float)KTOT);
    const float* src = weight + (size_t)o * KTOT;
    for (int j = tid; j < KTOT; j += 256) sm[j] = src[j];
    __syncthreads();
    const size_t ob = (size_t)o * KTOT;
    for (int k = tid; k < KTOT; k += 256) {
        const float v = sm[(k & 511) * KTAPS + (k >> 9)] * coef;
        const __nv_bfloat16 h = __float2bfloat16(v);
        g_Wh[ob + k] = h;
        g_Wl[ob + k] = __float2bfloat16(v - __bfloat162float(h));
    }
    for (int i = tid; i < CIN; i += 256) {
        float acc = 0.f;
#pragma unroll
        for (int t = 0; t < KTAPS; ++t) {
            const float v = sm[i * KTAPS + t] * coef;
            acc += v * v;
        }
        g_w2[i * COUT + o] = acc;
    }
}

// ---------------------------------------------------------------------------
// Prep 3: demod d[b,o] = rsqrt( sum_i w2[i,o] s[b,i]^2 + 1e-8 )
__global__ void prep_d() {
    const int b = blockIdx.x;
    const int o = threadIdx.x;
    __shared__ float s2[CIN];
    for (int i = threadIdx.x; i < CIN; i += blockDim.x) {
        const float s = g_s[b * CIN + i];
        s2[i] = s * s;
    }
    __syncthreads();
    float acc = 0.f;
#pragma unroll 8
    for (int i = 0; i < CIN; ++i)
        acc += g_w2[i * COUT + o] * s2[i];
    g_d[b * COUT + o] = rsqrtf(acc + 1e-8f);
}

// ---------------------------------------------------------------------------
// Prep 4: x -> transpose [b][p][i], scale by s[b,i], split hi/lo
__global__ void prep_xs(const float* __restrict__ x) {
    __shared__ float tile[32][33];
    const int b = blockIdx.z;
    const int p0 = blockIdx.x * 32;
    const int i0 = blockIdx.y * 32;
    const int tx = threadIdx.x, ty = threadIdx.y;
    const float* xb = x + ((size_t)b * CIN + i0) * NPIX + p0;
#pragma unroll
    for (int q = 0; q < 4; ++q) {
        const int r = ty * 4 + q;
        tile[r][tx] = xb[(size_t)r * NPIX + tx];
    }
    __syncthreads();
    const float sc = g_s[b * CIN + i0 + tx];
    const size_t ob = ((size_t)b * NPIX + p0) * CIN + i0;
#pragma unroll
    for (int q = 0; q < 4; ++q) {
        const int pl = ty * 4 + q;
        const float v = tile[tx][pl] * sc;
        const __nv_bfloat16 h = __float2bfloat16(v);
        g_xsh[ob + (size_t)pl * CIN + tx] = h;
        g_xsl[ob + (size_t)pl * CIN + tx] = __float2bfloat16(v - __bfloat162float(h));
    }
}

// ---------------------------------------------------------------------------
// Main conv: CTA 128 couts x 128 pixels, 4 warps (2x2), warp tile 64x64,
// split-bf16 3-pass HMMA, 3-stage cp.async pipeline.
__global__ __launch_bounds__(128)
void conv_main(const float* __restrict__ noise,
               const float* __restrict__ bias,
               const float* __restrict__ noise_scale,
               float* __restrict__ out) {
    extern __shared__ __align__(128) char sm[];

    const int b  = blockIdx.z;
    const int h0 = blockIdx.y * 2;
    const int o0 = blockIdx.x * 128;
    const int tid = threadIdx.x;
    const int wid = tid >> 5;
    const int lane = tid & 31;
    const int warp_m = wid & 1;
    const int warp_n = wid >> 1;

    const uint32_t sbase = s2u(sm);

    // ---- cp.async source/dst geometry (per thread row r = tid) ----
    const int r = tid;                          // 0..127 row in both tiles
    const int rsw = (r >> 1) & 3;               // swizzle key
    uint32_t dsw[4];
#pragma unroll
    for (int cc = 0; cc < 4; ++cc)
        dsw[cc] = (uint32_t)(r * 64 + ((cc ^ rsw) << 4));

    const __nv_bfloat16* aRowH = g_Wh + (size_t)(o0 + r) * KTOT;
    const __nv_bfloat16* aRowL = g_Wl + (size_t)(o0 + r) * KTOT;
    const size_t xbb = (size_t)b * NPIX;

    // ---- ldmatrix offsets (precomputed, per thread) ----
    uint32_t offA[4][2], offB[4][2];
#pragma unroll
    for (int mt = 0; mt < 4; ++mt) {
        const int row = warp_m * 64 + mt * 16 + (lane & 15);
        const int cb = lane >> 4;
#pragma unroll
        for (int j = 0; j < 2; ++j)
            offA[mt][j] = (uint32_t)(row * 64 + (((j * 2 + cb) ^ ((row >> 1) & 3)) << 4));
    }
#pragma unroll
    for (int q = 0; q < 4; ++q) {
        const int n = warp_n * 64 + q * 16 + (lane & 7) + ((lane >> 4) << 3);
        const int cb = (lane >> 3) & 1;
#pragma unroll
        for (int j = 0; j < 2; ++j)
            offB[q][j] = (uint32_t)(n * 64 + (((j * 2 + cb) ^ ((n >> 1) & 3)) << 4));
    }

    float acc[4][8][4];
#pragma unroll
    for (int mt = 0; mt < 4; ++mt)
#pragma unroll
        for (int nt = 0; nt < 8; ++nt)
#pragma unroll
            for (int e = 0; e < 4; ++e) acc[mt][nt][e] = 0.f;

    // ---- stage issue ----
    auto issue = [&](int c) {
        const int s = c % NSTAGE;
        const uint32_t base = sbase + (uint32_t)(s * STAGEB);
        const int t = c >> 4;                   // tap
        const int i0 = (c & 15) * 32;           // channel offset within tap
        const int k0 = c * 32;                  // global k
        // A tiles (hi, lo)
        const __nv_bfloat16* ah = aRowH + k0;
        const __nv_bfloat16* al = aRowL + k0;
#pragma unroll
        for (int cc = 0; cc < 4; ++cc) {
            cp_ca16(base + dsw[cc],             ah + cc * 8, 16);
            cp_ca16(base + TILEB + dsw[cc],     al + cc * 8, 16);
        }
        // B tiles (hi, lo) with halo predication (zero-fill via src-size 0)
        const int dy = t / 3 - 1;
        const int dx = t - (t / 3) * 3 - 1;
        const int hh = h0 + (r >> 6) + dy;
        const int ww = (r & 63) + dx;
        const bool ok = ((unsigned)hh < HH) & ((unsigned)ww < WW);
        const int sz = ok ? 16 : 0;
        const size_t px = ok ? (xbb + (size_t)hh * WW + ww) : xbb;
        const __nv_bfloat16* bh = g_xsh + px * CIN + i0;
        const __nv_bfloat16* bl = g_xsl + px * CIN + i0;
#pragma unroll
        for (int cc = 0; cc < 4; ++cc) {
            cp_cg16(base + 2 * TILEB + dsw[cc], bh + cc * 8, sz);
            cp_cg16(base + 3 * TILEB + dsw[cc], bl + cc * 8, sz);
        }
        cp_commit();
    };

    issue(0);
    issue(1);

    for (int c = 0; c < NCH; ++c) {
        cp_wait1();
        __syncthreads();
        if (c + 2 < NCH) issue(c + 2);
        else cp_commit();

        const uint32_t base = sbase + (uint32_t)((c % NSTAGE) * STAGEB);
        const uint32_t bAh = base;
        const uint32_t bAl = base + TILEB;
        const uint32_t bBh = base + 2 * TILEB;
        const uint32_t bBl = base + 3 * TILEB;

#pragma unroll
        for (int j = 0; j < 2; ++j) {
            uint32_t ah[4][4], al[4][4], bh[4][4], bl[4][4];
#pragma unroll
            for (int mt = 0; mt < 4; ++mt) {
                ldsm4(ah[mt], bAh + offA[mt][j]);
                ldsm4(al[mt], bAl + offA[mt][j]);
            }
#pragma unroll
            for (int q = 0; q < 4; ++q) {
                ldsm4(bh[q], bBh + offB[q][j]);
                ldsm4(bl[q], bBl + offB[q][j]);
            }
#pragma unroll
            for (int mt = 0; mt < 4; ++mt) {
#pragma unroll
                for (int nt = 0; nt < 8; ++nt) {
                    const int q = nt >> 1;
                    const int e = (nt & 1) * 2;
                    MMA(acc[mt][nt], ah[mt], bh[q][e], bh[q][e + 1]);
                    MMA(acc[mt][nt], ah[mt], bl[q][e], bl[q][e + 1]);
                    MMA(acc[mt][nt], al[mt], bh[q][e], bh[q][e + 1]);
                }
            }
        }
    }

    // ---- epilogue: demod, bias, noise, direct stores ----
    const float ns = noise_scale[0];
    const int hh = h0 + warp_n;
    const float* nrow = noise + ((size_t)b * HH + hh) * WW;
#pragma unroll
    for (int mt = 0; mt < 4; ++mt) {
        const int ob = o0 + warp_m * 64 + mt * 16 + (lane >> 2);
        const float d0 = g_d[b * COUT + ob];
        const float d1 = g_d[b * COUT + ob + 8];
        const float bb0 = bias[ob];
        const float bb1 = bias[ob + 8];
        float* orow0 = out + (((size_t)b * COUT + ob) * HH + hh) * WW;
        float* orow1 = orow0 + (size_t)8 * HH * WW;
#pragma unroll
        for (int nt = 0; nt < 8; ++nt) {
            const int w = nt * 8 + (lane & 3) * 2;
            const float2 nz = *(const float2*)(nrow + w);
            float2 v0, v1;
            v0.x = acc[mt][nt][0] * d0 + nz.x * ns + bb0;
            v0.y = acc[mt][nt][1] * d0 + nz.y * ns + bb0;
            v1.x = acc[mt][nt][2] * d1 + nz.x * ns + bb1;
            v1.y = acc[mt][nt][3] * d1 + nz.y * ns + bb1;
            *(float2*)(orow0 + w) = v0;
            *(float2*)(orow1 + w) = v1;
        }
    }
}

// ---------------------------------------------------------------------------
extern "C" void kernel_launch(void* const* d_in, const int* in_sizes, int n_in,
                              void* d_out, int out_size) {
    const float* x           = (const float*)d_in[0];
    const float* y           = (const float*)d_in[1];
    const float* noise       = (const float*)d_in[2];
    const float* weight      = (const float*)d_in[3];
    const float* bias        = (const float*)d_in[4];
    const float* mod_w       = (const float*)d_in[5];
    const float* mod_b       = (const float*)d_in[6];
    const float* noise_scale = (const float*)d_in[7];
    float* out = (float*)d_out;

    cudaFuncSetAttribute(conv_main, cudaFuncAttributeMaxDynamicSharedMemorySize, DYN_SMEM);

    prep_s<<<NB, CIN>>>(y, mod_w, mod_b);
    prep_w<<<COUT, 256>>>(weight);
    prep_d<<<NB, COUT>>>();
    prep_xs<<<dim3(NPIX / 32, CIN / 32, NB), dim3(32, 8)>>>(x);
    conv_main<<<dim3(COUT / 128, HH / 2, NB), 128, DYN_SMEM>>>(noise, bias, noise_scale, out);
}

// round 4
// speedup vs baseline: 6.0106x; 2.2579x over previous
#include <cuda_runtime.h>
#include <cuda_fp16.h>
#include <cstdint>

#define NB   16
#define CIN  512
#define COUT 512
#define HID  512
#define HH   64
#define WW   64
#define KTAPS 9
#define KTOT 4608
#define NPIX 4096

#define KC     64                  // fp16 K per chunk
#define NCH    (KTOT / KC)         // 72
#define TILEB  (128 * KC * 2)      // 16384 B per tile (128 rows x 128 B)
#define STAGEB (2 * TILEB)         // 32768 B (A + B)
#define NSTAGE 3
#define DYN_SMEM (NSTAGE * STAGEB) // 96 KB

// ---------------- static device scratch -------------------------------------
__device__ float g_s[NB * CIN];
__device__ float g_d[NB * COUT];
__device__ float g_w2[CIN * COUT];                 // sum_t w^2, [i][o]
__device__ __half g_Wh[(size_t)COUT * KTOT];       // scaled weights k-major fp16
__device__ __half g_xsh[(size_t)NB * NPIX * CIN];  // (x*s) [b][p][i] fp16

// ---------------- helpers ----------------------------------------------------
__device__ __forceinline__ uint32_t s2u(const void* p) {
    uint32_t a;
    asm("{ .reg .u64 t; cvta.to.shared.u64 t, %1; cvt.u32.u64 %0, t; }" : "=r"(a) : "l"(p));
    return a;
}
__device__ __forceinline__ void cp_ca16(uint32_t dst, const void* src) {
    asm volatile("cp.async.ca.shared.global [%0], [%1], 16;"
                 :: "r"(dst), "l"(src) : "memory");
}
__device__ __forceinline__ void cp_cg16(uint32_t dst, const void* src, int sz) {
    asm volatile("cp.async.cg.shared.global [%0], [%1], 16, %2;"
                 :: "r"(dst), "l"(src), "r"(sz) : "memory");
}
__device__ __forceinline__ void cp_commit() {
    asm volatile("cp.async.commit_group;" ::: "memory");
}
__device__ __forceinline__ void cp_wait1() {
    asm volatile("cp.async.wait_group 1;" ::: "memory");
}
__device__ __forceinline__ void ldsm4(uint32_t* r, uint32_t addr) {
    asm volatile("ldmatrix.sync.aligned.m8n8.x4.shared.b16 {%0,%1,%2,%3}, [%4];"
                 : "=r"(r[0]), "=r"(r[1]), "=r"(r[2]), "=r"(r[3]) : "r"(addr));
}
#define MMA(c, a, B0, B1) \
    asm volatile("mma.sync.aligned.m16n8k16.row.col.f32.f16.f16.f32 " \
                 "{%0,%1,%2,%3},{%4,%5,%6,%7},{%8,%9},{%0,%1,%2,%3};" \
                 : "+f"((c)[0]), "+f"((c)[1]), "+f"((c)[2]), "+f"((c)[3]) \
                 : "r"((a)[0]), "r"((a)[1]), "r"((a)[2]), "r"((a)[3]), \
                   "r"(B0), "r"(B1))

// ---------------------------------------------------------------------------
// Prep 1: style s[b,i]
__global__ void prep_s(const float* __restrict__ y,
                       const float* __restrict__ mod_w,
                       const float* __restrict__ mod_b) {
    const int b = blockIdx.x;
    const int i = threadIdx.x;
    const float ms = rsqrtf((float)HID);
    const float4* yr = (const float4*)(y + (size_t)b * HID);
    const float4* wr = (const float4*)(mod_w + (size_t)i * HID);
    float acc = 0.f;
#pragma unroll 8
    for (int h = 0; h < HID / 4; ++h) {
        float4 a = yr[h];
        float4 w = wr[h];
        acc += a.x * w.x + a.y * w.y + a.z * w.z + a.w * w.w;
    }
    g_s[b * CIN + i] = acc * ms + mod_b[i] + 1.0f;
}

// ---------------------------------------------------------------------------
// Prep 2: scaled weights -> k-major fp16 (k = t*512 + i), plus g_w2[i][o]
__global__ void prep_w(const float* __restrict__ weight) {
    __shared__ float sm[KTOT];
    const int o = blockIdx.x;
    const int tid = threadIdx.x;
    const float coef = rsqrtf((float)KTOT);
    const float* src = weight + (size_t)o * KTOT;
    for (int j = tid; j < KTOT; j += 256) sm[j] = src[j];
    __syncthreads();
    const size_t ob = (size_t)o * KTOT;
    for (int k = tid; k < KTOT; k += 256)
        g_Wh[ob + k] = __float2half(sm[(k & 511) * KTAPS + (k >> 9)] * coef);
    for (int i = tid; i < CIN; i += 256) {
        float acc = 0.f;
#pragma unroll
        for (int t = 0; t < KTAPS; ++t) {
            const float v = sm[i * KTAPS + t] * coef;
            acc += v * v;
        }
        g_w2[i * COUT + o] = acc;
    }
}

// ---------------------------------------------------------------------------
// Prep 3: demod d[b,o] = rsqrt( sum_i w2[i,o] s[b,i]^2 + 1e-8 )
__global__ void prep_d() {
    const int b = blockIdx.x;
    const int o = threadIdx.x;
    __shared__ float s2[CIN];
    for (int i = threadIdx.x; i < CIN; i += blockDim.x) {
        const float s = g_s[b * CIN + i];
        s2[i] = s * s;
    }
    __syncthreads();
    float acc = 0.f;
#pragma unroll 8
    for (int i = 0; i < CIN; ++i)
        acc += g_w2[i * COUT + o] * s2[i];
    g_d[b * COUT + o] = rsqrtf(acc + 1e-8f);
}

// ---------------------------------------------------------------------------
// Prep 4: x -> transpose [b][p][i], scale by s[b,i], fp16
__global__ void prep_xs(const float* __restrict__ x) {
    __shared__ float tile[32][33];
    const int b = blockIdx.z;
    const int p0 = blockIdx.x * 32;
    const int i0 = blockIdx.y * 32;
    const int tx = threadIdx.x, ty = threadIdx.y;
    const float* xb = x + ((size_t)b * CIN + i0) * NPIX + p0;
#pragma unroll
    for (int q = 0; q < 4; ++q) {
        const int r = ty * 4 + q;
        tile[r][tx] = xb[(size_t)r * NPIX + tx];
    }
    __syncthreads();
    const float sc = g_s[b * CIN + i0 + tx];
    const size_t ob = ((size_t)b * NPIX + p0) * CIN + i0;
#pragma unroll
    for (int q = 0; q < 4; ++q) {
        const int pl = ty * 4 + q;
        g_xsh[ob + (size_t)pl * CIN + tx] = __float2half(tile[tx][pl] * sc);
    }
}

// ---------------------------------------------------------------------------
// Main conv: CTA 128 couts x 128 pixels, 4 warps (2x2), warp tile 64x64,
// single-pass fp16 HMMA, 3-stage cp.async pipeline, KC=64.
__global__ __launch_bounds__(128)
void conv_main(const float* __restrict__ noise,
               const float* __restrict__ bias,
               const float* __restrict__ noise_scale,
               float* __restrict__ out) {
    extern __shared__ __align__(128) char sm[];

    const int b  = blockIdx.z;
    const int h0 = blockIdx.y * 2;
    const int o0 = blockIdx.x * 128;
    const int tid = threadIdx.x;
    const int wid = tid >> 5;
    const int lane = tid & 31;
    const int warp_m = wid & 1;
    const int warp_n = wid >> 1;

    const uint32_t sbase = s2u(sm);

    // ---- cp.async geometry: thread owns row r (128B), 8 swizzled 16B chunks
    const int r = tid;
    uint32_t dsw[8];
#pragma unroll
    for (int cc = 0; cc < 8; ++cc)
        dsw[cc] = (uint32_t)(r * 128 + ((cc ^ (r & 7)) << 4));

    const __half* aRow = g_Wh + (size_t)(o0 + r) * KTOT;
    const size_t xbb = (size_t)b * NPIX;

    // ---- ldmatrix base offsets (j=0); addr(j) = addr(0) ^ (j<<5)
    uint32_t offA0[4], offB0[4];
#pragma unroll
    for (int mt = 0; mt < 4; ++mt) {
        const int row = warp_m * 64 + mt * 16 + (lane & 15);
        offA0[mt] = (uint32_t)(row * 128 + (((lane >> 4) ^ (row & 7)) << 4));
    }
#pragma unroll
    for (int q = 0; q < 4; ++q) {
        const int n = warp_n * 64 + q * 16 + (lane & 7) + ((lane >> 4) << 3);
        offB0[q] = (uint32_t)(n * 128 + ((((lane >> 3) & 1) ^ (n & 7)) << 4));
    }

    float acc[4][8][4];
#pragma unroll
    for (int mt = 0; mt < 4; ++mt)
#pragma unroll
        for (int nt = 0; nt < 8; ++nt)
#pragma unroll
            for (int e = 0; e < 4; ++e) acc[mt][nt][e] = 0.f;

    // ---- stage issue ----
    auto issue = [&](int c) {
        const int s = c % NSTAGE;
        const uint32_t base = sbase + (uint32_t)(s * STAGEB);
        const int t  = c >> 3;            // tap 0..8
        const int i0 = (c & 7) * 64;      // channel offset within tap
        const int k0 = c * 64;            // global k
        const __half* ah = aRow + k0;
#pragma unroll
        for (int cc = 0; cc < 8; ++cc)
            cp_ca16(base + dsw[cc], ah + cc * 8);

        const int dy = t / 3 - 1;
        const int dx = t - (t / 3) * 3 - 1;
        const int hh = h0 + (r >> 6) + dy;
        const int ww = (r & 63) + dx;
        const bool ok = ((unsigned)hh < HH) & ((unsigned)ww < WW);
        const int sz = ok ? 16 : 0;
        const size_t px = ok ? (xbb + (size_t)hh * WW + ww) : xbb;
        const __half* bh = g_xsh + px * CIN + i0;
#pragma unroll
        for (int cc = 0; cc < 8; ++cc)
            cp_cg16(base + TILEB + dsw[cc], bh + cc * 8, sz);
        cp_commit();
    };

    issue(0);
    issue(1);

    for (int c = 0; c < NCH; ++c) {
        cp_wait1();
        __syncthreads();
        if (c + 2 < NCH) issue(c + 2);
        else cp_commit();

        const uint32_t base = sbase + (uint32_t)((c % NSTAGE) * STAGEB);
        const uint32_t bA = base;
        const uint32_t bB = base + TILEB;

#pragma unroll
        for (int j = 0; j < 4; ++j) {
            const uint32_t jx = (uint32_t)(j << 5);
            uint32_t ah[4][4], bh[4][4];
#pragma unroll
            for (int mt = 0; mt < 4; ++mt) ldsm4(ah[mt], bA + (offA0[mt] ^ jx));
#pragma unroll
            for (int q = 0; q < 4; ++q)   ldsm4(bh[q], bB + (offB0[q] ^ jx));
#pragma unroll
            for (int mt = 0; mt < 4; ++mt)
#pragma unroll
                for (int nt = 0; nt < 8; ++nt) {
                    const int q = nt >> 1;
                    const int e = (nt & 1) * 2;
                    MMA(acc[mt][nt], ah[mt], bh[q][e], bh[q][e + 1]);
                }
        }
        __syncthreads();
    }

    // ---- epilogue: demod, bias, noise, direct stores ----
    const float ns = noise_scale[0];
    const int hh = h0 + warp_n;
    const float* nrow = noise + ((size_t)b * HH + hh) * WW;
#pragma unroll
    for (int mt = 0; mt < 4; ++mt) {
        const int ob = o0 + warp_m * 64 + mt * 16 + (lane >> 2);
        const float d0 = g_d[b * COUT + ob];
        const float d1 = g_d[b * COUT + ob + 8];
        const float bb0 = bias[ob];
        const float bb1 = bias[ob + 8];
        float* orow0 = out + (((size_t)b * COUT + ob) * HH + hh) * WW;
        float* orow1 = orow0 + (size_t)8 * HH * WW;
#pragma unroll
        for (int nt = 0; nt < 8; ++nt) {
            const int w = nt * 8 + (lane & 3) * 2;
            const float2 nz = *(const float2*)(nrow + w);
            float2 v0, v1;
            v0.x = acc[mt][nt][0] * d0 + nz.x * ns + bb0;
            v0.y = acc[mt][nt][1] * d0 + nz.y * ns + bb0;
            v1.x = acc[mt][nt][2] * d1 + nz.x * ns + bb1;
            v1.y = acc[mt][nt][3] * d1 + nz.y * ns + bb1;
            *(float2*)(orow0 + w) = v0;
            *(float2*)(orow1 + w) = v1;
        }
    }
}

// ---------------------------------------------------------------------------
extern "C" void kernel_launch(void* const* d_in, const int* in_sizes, int n_in,
                              void* d_out, int out_size) {
    const float* x           = (const float*)d_in[0];
    const float* y           = (const float*)d_in[1];
    const float* noise       = (const float*)d_in[2];
    const float* weight      = (const float*)d_in[3];
    const float* bias        = (const float*)d_in[4];
    const float* mod_w       = (const float*)d_in[5];
    const float* mod_b       = (const float*)d_in[6];
    const float* noise_scale = (const float*)d_in[7];
    float* out = (float*)d_out;

    cudaFuncSetAttribute(conv_main, cudaFuncAttributeMaxDynamicSharedMemorySize, DYN_SMEM);

    prep_s<<<NB, CIN>>>(y, mod_w, mod_b);
    prep_w<<<COUT, 256>>>(weight);
    prep_d<<<NB, COUT>>>();
    prep_xs<<<dim3(NPIX / 32, CIN / 32, NB), dim3(32, 8)>>>(x);
    conv_main<<<dim3(COUT / 128, HH / 2, NB), 128, DYN_SMEM>>>(noise, bias, noise_scale, out);
}

// round 5
// speedup vs baseline: 6.2186x; 1.0346x over previous
#include <cuda_runtime.h>
#include <cuda_fp16.h>
#include <cstdint>

#define NB   16
#define CIN  512
#define COUT 512
#define HID  512
#define HH   64
#define WW   64
#define KTAPS 9
#define KTOT 4608
#define NPIX 4096

#define KC     64                  // fp16 K per chunk
#define NCH    (KTOT / KC)         // 72
#define TILEB  (128 * KC * 2)      // 16384 B per tile (128 rows x 128 B)
#define STAGEB (2 * TILEB)         // 32768 B (A + B)
#define NSTAGE 3
#define DYN_SMEM (NSTAGE * STAGEB) // 96 KB

// ---------------- static device scratch -------------------------------------
__device__ float g_s[NB * CIN];
__device__ float g_d[NB * COUT];
__device__ float g_w2[CIN * COUT];                 // sum_t w^2, [i][o]
__device__ __half g_Wh[(size_t)COUT * KTOT];       // scaled weights k-major fp16
__device__ __half g_xsh[(size_t)NB * NPIX * CIN];  // (x*s) [b][p][i] fp16

// ---------------- helpers ----------------------------------------------------
__device__ __forceinline__ uint32_t s2u(const void* p) {
    uint32_t a;
    asm("{ .reg .u64 t; cvta.to.shared.u64 t, %1; cvt.u32.u64 %0, t; }" : "=r"(a) : "l"(p));
    return a;
}
__device__ __forceinline__ void cp_ca16(uint32_t dst, const void* src) {
    asm volatile("cp.async.ca.shared.global [%0], [%1], 16;"
                 :: "r"(dst), "l"(src) : "memory");
}
__device__ __forceinline__ void cp_cg16(uint32_t dst, const void* src, int sz) {
    asm volatile("cp.async.cg.shared.global [%0], [%1], 16, %2;"
                 :: "r"(dst), "l"(src), "r"(sz) : "memory");
}
__device__ __forceinline__ void cp_commit() {
    asm volatile("cp.async.commit_group;" ::: "memory");
}
__device__ __forceinline__ void cp_wait1() {
    asm volatile("cp.async.wait_group 1;" ::: "memory");
}
__device__ __forceinline__ void ldsm4(uint32_t* r, uint32_t addr) {
    asm volatile("ldmatrix.sync.aligned.m8n8.x4.shared.b16 {%0,%1,%2,%3}, [%4];"
                 : "=r"(r[0]), "=r"(r[1]), "=r"(r[2]), "=r"(r[3]) : "r"(addr));
}
#define MMA(c, a, B0, B1) \
    asm volatile("mma.sync.aligned.m16n8k16.row.col.f32.f16.f16.f32 " \
                 "{%0,%1,%2,%3},{%4,%5,%6,%7},{%8,%9},{%0,%1,%2,%3};" \
                 : "+f"((c)[0]), "+f"((c)[1]), "+f"((c)[2]), "+f"((c)[3]) \
                 : "r"((a)[0]), "r"((a)[1]), "r"((a)[2]), "r"((a)[3]), \
                   "r"(B0), "r"(B1))

// ---------------------------------------------------------------------------
// Prep 1: style s[b,i]
__global__ void prep_s(const float* __restrict__ y,
                       const float* __restrict__ mod_w,
                       const float* __restrict__ mod_b) {
    const int b = blockIdx.x;
    const int i = threadIdx.x;
    const float ms = rsqrtf((float)HID);
    const float4* yr = (const float4*)(y + (size_t)b * HID);
    const float4* wr = (const float4*)(mod_w + (size_t)i * HID);
    float acc = 0.f;
#pragma unroll 8
    for (int h = 0; h < HID / 4; ++h) {
        float4 a = yr[h];
        float4 w = wr[h];
        acc += a.x * w.x + a.y * w.y + a.z * w.z + a.w * w.w;
    }
    g_s[b * CIN + i] = acc * ms + mod_b[i] + 1.0f;
}

// ---------------------------------------------------------------------------
// Prep 2: scaled weights -> k-major fp16 (k = t*512 + i), plus g_w2[i][o]
__global__ void prep_w(const float* __restrict__ weight) {
    __shared__ float sm[KTOT];
    const int o = blockIdx.x;
    const int tid = threadIdx.x;
    const float coef = rsqrtf((float)KTOT);
    const float* src = weight + (size_t)o * KTOT;
    for (int j = tid; j < KTOT; j += 256) sm[j] = src[j];
    __syncthreads();
    const size_t ob = (size_t)o * KTOT;
    for (int k = tid; k < KTOT; k += 256)
        g_Wh[ob + k] = __float2half(sm[(k & 511) * KTAPS + (k >> 9)] * coef);
    for (int i = tid; i < CIN; i += 256) {
        float acc = 0.f;
#pragma unroll
        for (int t = 0; t < KTAPS; ++t) {
            const float v = sm[i * KTAPS + t] * coef;
            acc += v * v;
        }
        g_w2[i * COUT + o] = acc;
    }
}

// ---------------------------------------------------------------------------
// Prep 3: demod d[b,o] = rsqrt( sum_i w2[i,o] s[b,i]^2 + 1e-8 )
__global__ void prep_d() {
    const int b = blockIdx.x;
    const int o = threadIdx.x;
    __shared__ float s2[CIN];
    for (int i = threadIdx.x; i < CIN; i += blockDim.x) {
        const float s = g_s[b * CIN + i];
        s2[i] = s * s;
    }
    __syncthreads();
    float acc = 0.f;
#pragma unroll 8
    for (int i = 0; i < CIN; ++i)
        acc += g_w2[i * COUT + o] * s2[i];
    g_d[b * COUT + o] = rsqrtf(acc + 1e-8f);
}

// ---------------------------------------------------------------------------
// Prep 4: x -> transpose [b][p][i], scale by s[b,i], fp16
__global__ void prep_xs(const float* __restrict__ x) {
    __shared__ float tile[32][33];
    const int b = blockIdx.z;
    const int p0 = blockIdx.x * 32;
    const int i0 = blockIdx.y * 32;
    const int tx = threadIdx.x, ty = threadIdx.y;
    const float* xb = x + ((size_t)b * CIN + i0) * NPIX + p0;
#pragma unroll
    for (int q = 0; q < 4; ++q) {
        const int r = ty * 4 + q;
        tile[r][tx] = xb[(size_t)r * NPIX + tx];
    }
    __syncthreads();
    const float sc = g_s[b * CIN + i0 + tx];
    const size_t ob = ((size_t)b * NPIX + p0) * CIN + i0;
#pragma unroll
    for (int q = 0; q < 4; ++q) {
        const int pl = ty * 4 + q;
        g_xsh[ob + (size_t)pl * CIN + tx] = __float2half(tile[tx][pl] * sc);
    }
}

// ---------------------------------------------------------------------------
// Main conv: CTA 128 couts x 128 pixels, 8 warps (4x2), warp tile 32x64,
// single-pass fp16 HMMA, 3-stage cp.async pipeline, KC=64.
__global__ __launch_bounds__(256, 2)
void conv_main(const float* __restrict__ noise,
               const float* __restrict__ bias,
               const float* __restrict__ noise_scale,
               float* __restrict__ out) {
    extern __shared__ __align__(128) char sm[];

    const int b  = blockIdx.z;
    const int h0 = blockIdx.y * 2;
    const int o0 = blockIdx.x * 128;
    const int tid = threadIdx.x;
    const int wid = tid >> 5;
    const int lane = tid & 31;
    const int warp_m = wid & 3;    // 0..3 -> 32-row m block
    const int warp_n = wid >> 2;   // 0..1 -> 64-col n block

    const uint32_t sbase = s2u(sm);

    // ---- cp.async geometry: threads 0..127 fill A rows, 128..255 fill B rows
    const bool isA = (tid < 128);
    const int r = tid & 127;                 // row within its tile
    uint32_t dsw[8];
#pragma unroll
    for (int cc = 0; cc < 8; ++cc)
        dsw[cc] = (uint32_t)((isA ? 0 : TILEB) + r * 128 + ((cc ^ (r & 7)) << 4));

    const __half* aRow = g_Wh + (size_t)(o0 + r) * KTOT;
    const size_t xbb = (size_t)b * NPIX;

    // ---- ldmatrix base offsets (j=0); addr(j) = addr(0) ^ (j<<5)
    uint32_t offA0[2], offB0[4];
#pragma unroll
    for (int mt = 0; mt < 2; ++mt) {
        const int row = warp_m * 32 + mt * 16 + (lane & 15);
        offA0[mt] = (uint32_t)(row * 128 + (((lane >> 4) ^ (row & 7)) << 4));
    }
#pragma unroll
    for (int q = 0; q < 4; ++q) {
        const int n = warp_n * 64 + q * 16 + (lane & 7) + ((lane >> 4) << 3);
        offB0[q] = (uint32_t)(n * 128 + ((((lane >> 3) & 1) ^ (n & 7)) << 4));
    }

    float acc[2][8][4];
#pragma unroll
    for (int mt = 0; mt < 2; ++mt)
#pragma unroll
        for (int nt = 0; nt < 8; ++nt)
#pragma unroll
            for (int e = 0; e < 4; ++e) acc[mt][nt][e] = 0.f;

    // ---- stage issue ----
    auto issue = [&](int c) {
        const int s = c % NSTAGE;
        const uint32_t base = sbase + (uint32_t)(s * STAGEB);
        if (isA) {
            const __half* ah = aRow + c * 64;
#pragma unroll
            for (int cc = 0; cc < 8; ++cc)
                cp_ca16(base + dsw[cc], ah + cc * 8);
        } else {
            const int t  = c >> 3;            // tap 0..8
            const int i0 = (c & 7) * 64;      // channel offset within tap
            const int dy = t / 3 - 1;
            const int dx = t - (t / 3) * 3 - 1;
            const int hh = h0 + (r >> 6) + dy;
            const int ww = (r & 63) + dx;
            const bool ok = ((unsigned)hh < HH) & ((unsigned)ww < WW);
            const int sz = ok ? 16 : 0;
            const size_t px = ok ? (xbb + (size_t)hh * WW + ww) : xbb;
            const __half* bh = g_xsh + px * CIN + i0;
#pragma unroll
            for (int cc = 0; cc < 8; ++cc)
                cp_cg16(base + dsw[cc], bh + cc * 8, sz);
        }
        cp_commit();
    };

    issue(0);
    issue(1);

    for (int c = 0; c < NCH; ++c) {
        cp_wait1();
        __syncthreads();
        if (c + 2 < NCH) issue(c + 2);
        else cp_commit();

        const uint32_t base = sbase + (uint32_t)((c % NSTAGE) * STAGEB);
        const uint32_t bA = base;
        const uint32_t bB = base + TILEB;

#pragma unroll
        for (int j = 0; j < 4; ++j) {
            const uint32_t jx = (uint32_t)(j << 5);
            uint32_t ah[2][4], bh[4][4];
#pragma unroll
            for (int mt = 0; mt < 2; ++mt) ldsm4(ah[mt], bA + (offA0[mt] ^ jx));
#pragma unroll
            for (int q = 0; q < 4; ++q)   ldsm4(bh[q], bB + (offB0[q] ^ jx));
#pragma unroll
            for (int mt = 0; mt < 2; ++mt)
#pragma unroll
                for (int nt = 0; nt < 8; ++nt) {
                    const int q = nt >> 1;
                    const int e = (nt & 1) * 2;
                    MMA(acc[mt][nt], ah[mt], bh[q][e], bh[q][e + 1]);
                }
        }
        __syncthreads();
    }

    // ---- epilogue: demod, bias, noise, direct stores ----
    const float ns = noise_scale[0];
    const int hh = h0 + warp_n;
    const float* nrow = noise + ((size_t)b * HH + hh) * WW;
#pragma unroll
    for (int mt = 0; mt < 2; ++mt) {
        const int ob = o0 + warp_m * 32 + mt * 16 + (lane >> 2);
        const float d0 = g_d[b * COUT + ob];
        const float d1 = g_d[b * COUT + ob + 8];
        const float bb0 = bias[ob];
        const float bb1 = bias[ob + 8];
        float* orow0 = out + (((size_t)b * COUT + ob) * HH + hh) * WW;
        float* orow1 = orow0 + (size_t)8 * HH * WW;
#pragma unroll
        for (int nt = 0; nt < 8; ++nt) {
            const int w = nt * 8 + (lane & 3) * 2;
            const float2 nz = *(const float2*)(nrow + w);
            float2 v0, v1;
            v0.x = acc[mt][nt][0] * d0 + nz.x * ns + bb0;
            v0.y = acc[mt][nt][1] * d0 + nz.y * ns + bb0;
            v1.x = acc[mt][nt][2] * d1 + nz.x * ns + bb1;
            v1.y = acc[mt][nt][3] * d1 + nz.y * ns + bb1;
            *(float2*)(orow0 + w) = v0;
            *(float2*)(orow1 + w) = v1;
        }
    }
}

// ---------------------------------------------------------------------------
extern "C" void kernel_launch(void* const* d_in, const int* in_sizes, int n_in,
                              void* d_out, int out_size) {
    const float* x           = (const float*)d_in[0];
    const float* y           = (const float*)d_in[1];
    const float* noise       = (const float*)d_in[2];
    const float* weight      = (const float*)d_in[3];
    const float* bias        = (const float*)d_in[4];
    const float* mod_w       = (const float*)d_in[5];
    const float* mod_b       = (const float*)d_in[6];
    const float* noise_scale = (const float*)d_in[7];
    float* out = (float*)d_out;

    cudaFuncSetAttribute(conv_main, cudaFuncAttributeMaxDynamicSharedMemorySize, DYN_SMEM);

    prep_s<<<NB, CIN>>>(y, mod_w, mod_b);
    prep_w<<<COUT, 256>>>(weight);
    prep_d<<<NB, COUT>>>();
    prep_xs<<<dim3(NPIX / 32, CIN / 32, NB), dim3(32, 8)>>>(x);
    conv_main<<<dim3(COUT / 128, HH / 2, NB), 256, DYN_SMEM>>>(noise, bias, noise_scale, out);
}

// round 6
// speedup vs baseline: 8.8385x; 1.4213x over previous
#include <cuda_runtime.h>
#include <cuda_fp16.h>
#include <cstdint>

#define NB   16
#define CIN  512
#define COUT 512
#define HID  512
#define HH   64
#define WW   64
#define NT   16384                 // 16 batches x 32x32 output tiles

// GEMM tiling (per Winograd coordinate): M=COUT, N=NT, K=CIN
#define KC     64
#define NCH    (CIN / KC)          // 8
#define TILEB  (128 * KC * 2)      // 16384 B
#define STAGEB (2 * TILEB)
#define NSTAGE 3
#define DYN_GEMM (NSTAGE * STAGEB) // 96 KB
#define DYN_INTF (34816 + 40960)   // xs plane + stage

// ---------------- static device scratch -------------------------------------
__device__ float g_s[NB * CIN];
__device__ float g_d[NB * COUT];
__device__ float g_w2[CIN * COUT];
__device__ __half g_U[(size_t)16 * COUT * CIN];   // [coord][o][i]
__device__ __half g_V[(size_t)16 * NT * CIN];     // [coord][tile][i]
__device__ float  g_M[(size_t)16 * COUT * NT];    // [coord][o][tile]

// ---------------- helpers ----------------------------------------------------
__device__ __forceinline__ uint32_t s2u(const void* p) {
    uint32_t a;
    asm("{ .reg .u64 t; cvta.to.shared.u64 t, %1; cvt.u32.u64 %0, t; }" : "=r"(a) : "l"(p));
    return a;
}
__device__ __forceinline__ void cp_ca16(uint32_t dst, const void* src) {
    asm volatile("cp.async.ca.shared.global [%0], [%1], 16;"
                 :: "r"(dst), "l"(src) : "memory");
}
__device__ __forceinline__ void cp_cg16(uint32_t dst, const void* src) {
    asm volatile("cp.async.cg.shared.global [%0], [%1], 16;"
                 :: "r"(dst), "l"(src) : "memory");
}
__device__ __forceinline__ void cp_commit() {
    asm volatile("cp.async.commit_group;" ::: "memory");
}
__device__ __forceinline__ void cp_wait1() {
    asm volatile("cp.async.wait_group 1;" ::: "memory");
}
__device__ __forceinline__ void ldsm4(uint32_t* r, uint32_t addr) {
    asm volatile("ldmatrix.sync.aligned.m8n8.x4.shared.b16 {%0,%1,%2,%3}, [%4];"
                 : "=r"(r[0]), "=r"(r[1]), "=r"(r[2]), "=r"(r[3]) : "r"(addr));
}
#define MMA(c, a, B0, B1) \
    asm volatile("mma.sync.aligned.m16n8k16.row.col.f32.f16.f16.f32 " \
                 "{%0,%1,%2,%3},{%4,%5,%6,%7},{%8,%9},{%0,%1,%2,%3};" \
                 : "+f"((c)[0]), "+f"((c)[1]), "+f"((c)[2]), "+f"((c)[3]) \
                 : "r"((a)[0]), "r"((a)[1]), "r"((a)[2]), "r"((a)[3]), \
                   "r"(B0), "r"(B1))

// ---------------------------------------------------------------------------
// Prep 1: style s[b,i]
__global__ void prep_s(const float* __restrict__ y,
                       const float* __restrict__ mod_w,
                       const float* __restrict__ mod_b) {
    const int b = blockIdx.x;
    const int i = threadIdx.x;
    const float ms = rsqrtf((float)HID);
    const float4* yr = (const float4*)(y + (size_t)b * HID);
    const float4* wr = (const float4*)(mod_w + (size_t)i * HID);
    float acc = 0.f;
#pragma unroll 8
    for (int h = 0; h < HID / 4; ++h) {
        float4 a = yr[h];
        float4 w = wr[h];
        acc += a.x * w.x + a.y * w.y + a.z * w.z + a.w * w.w;
    }
    g_s[b * CIN + i] = acc * ms + mod_b[i] + 1.0f;
}

// ---------------------------------------------------------------------------
// Prep 2: Winograd weight transform U = G g G^T (fp32, round once to fp16)
// grid = COUT blocks, CIN threads. Also emits g_w2[i][o] for demod.
__global__ void prep_U(const float* __restrict__ weight) {
    const int o = blockIdx.x;
    const int i = threadIdx.x;
    const float coef = rsqrtf((float)(CIN * 9));
    const float* wp = weight + ((size_t)o * CIN + i) * 9;
    float g[3][3];
    float ss = 0.f;
#pragma unroll
    for (int r = 0; r < 3; ++r)
#pragma unroll
        for (int c = 0; c < 3; ++c) {
            const float v = wp[r * 3 + c] * coef;
            g[r][c] = v;
            ss += v * v;
        }
    g_w2[i * COUT + o] = ss;

    float T[4][3];
#pragma unroll
    for (int c = 0; c < 3; ++c) {
        T[0][c] = g[0][c];
        T[1][c] = 0.5f * (g[0][c] + g[1][c] + g[2][c]);
        T[2][c] = 0.5f * (g[0][c] - g[1][c] + g[2][c]);
        T[3][c] = g[2][c];
    }
    const size_t base = (size_t)o * CIN + i;
#pragma unroll
    for (int r = 0; r < 4; ++r) {
        float u0 = T[r][0];
        float u1 = 0.5f * (T[r][0] + T[r][1] + T[r][2]);
        float u2 = 0.5f * (T[r][0] - T[r][1] + T[r][2]);
        float u3 = T[r][2];
        g_U[(size_t)(r * 4 + 0) * COUT * CIN + base] = __float2half(u0);
        g_U[(size_t)(r * 4 + 1) * COUT * CIN + base] = __float2half(u1);
        g_U[(size_t)(r * 4 + 2) * COUT * CIN + base] = __float2half(u2);
        g_U[(size_t)(r * 4 + 3) * COUT * CIN + base] = __float2half(u3);
    }
}

// ---------------------------------------------------------------------------
// Prep 3: demod d[b,o]
__global__ void prep_d() {
    const int b = blockIdx.x;
    const int o = threadIdx.x;
    __shared__ float s2[CIN];
    for (int i = threadIdx.x; i < CIN; i += blockDim.x) {
        const float s = g_s[b * CIN + i];
        s2[i] = s * s;
    }
    __syncthreads();
    float acc = 0.f;
#pragma unroll 8
    for (int i = 0; i < CIN; ++i)
        acc += g_w2[i * COUT + o] * s2[i];
    g_d[b * COUT + o] = rsqrtf(acc + 1e-8f);
}

// ---------------------------------------------------------------------------
// Input transform: V[coord][b*1024 + ty*32 + tx][i] = (B^T (x*s) B), fp16.
// grid (32 ty, 16 i-chunk, 16 b), 256 threads.
__global__ __launch_bounds__(256) void in_tf(const float* __restrict__ x) {
    extern __shared__ __align__(16) char smraw[];
    float* xs = (float*)smraw;                       // [32 i][4 r][68 cols] padded
    __half* stage = (__half*)(smraw + 34816);        // [16 c][32 tx][40 pad]

    const int ty = blockIdx.x;
    const int ic = blockIdx.y;
    const int b  = blockIdx.z;
    const int i0 = ic * 32;
    const int tid = threadIdx.x;
    const int lane = tid & 31;
    const int wid = tid >> 5;

    for (int idx = tid; idx < 32 * 4 * 68; idx += 256) xs[idx] = 0.f;
    __syncthreads();

    const int r0 = 2 * ty - 1;
#pragma unroll
    for (int k = 0; k < 8; ++k) {
        const int f4 = tid + 256 * k;
        const int i_l = f4 >> 6;
        const int r = (f4 >> 4) & 3;
        const int w0 = (f4 & 15) * 4;
        const int row = r0 + r;
        if ((unsigned)row < HH) {
            const float sc = g_s[b * CIN + i0 + i_l];
            const float4 v = *(const float4*)(x + (((size_t)(b * CIN + i0 + i_l)) * HH + row) * WW + w0);
            float* dst = &xs[(i_l * 4 + r) * 68 + 1 + w0];
            dst[0] = v.x * sc; dst[1] = v.y * sc; dst[2] = v.z * sc; dst[3] = v.w * sc;
        }
    }
    __syncthreads();

#pragma unroll
    for (int q = 0; q < 4; ++q) {
        const int i_l = wid + 8 * q;
        const int tx = lane;
        const float* base = &xs[(i_l * 4) * 68 + 2 * tx];
        float d[4][4];
#pragma unroll
        for (int r = 0; r < 4; ++r)
#pragma unroll
            for (int c = 0; c < 4; ++c)
                d[r][c] = base[r * 68 + c];
        float t[4][4];
#pragma unroll
        for (int c = 0; c < 4; ++c) {
            t[0][c] = d[0][c] - d[2][c];
            t[1][c] = d[1][c] + d[2][c];
            t[2][c] = d[2][c] - d[1][c];
            t[3][c] = d[1][c] - d[3][c];
        }
#pragma unroll
        for (int r = 0; r < 4; ++r) {
            const float v0 = t[r][0] - t[r][2];
            const float v1 = t[r][1] + t[r][2];
            const float v2 = t[r][2] - t[r][1];
            const float v3 = t[r][1] - t[r][3];
            stage[((r * 4 + 0) * 32 + tx) * 40 + i_l] = __float2half(v0);
            stage[((r * 4 + 1) * 32 + tx) * 40 + i_l] = __float2half(v1);
            stage[((r * 4 + 2) * 32 + tx) * 40 + i_l] = __float2half(v2);
            stage[((r * 4 + 3) * 32 + tx) * 40 + i_l] = __float2half(v3);
        }
    }
    __syncthreads();

    const size_t nbase = (size_t)b * 1024 + ty * 32;
#pragma unroll
    for (int k = 0; k < 2; ++k) {
        const int p = tid + 256 * k;
        const int c16 = p >> 5;
        const int tx = p & 31;
        const uint4* src = (const uint4*)&stage[((size_t)c16 * 32 + tx) * 40];
        uint4* dst = (uint4*)(g_V + ((size_t)c16 * NT + nbase + tx) * CIN + i0);
        dst[0] = src[0]; dst[1] = src[1]; dst[2] = src[2]; dst[3] = src[3];
    }
}

// ---------------------------------------------------------------------------
// Winograd GEMM: per coord z, D[o, tile] = sum_i U[z][o][i] V[z][tile][i].
// CTA 128x128, 8 warps (4x2), warp 32x64, fp16 HMMA, 3-stage cp.async.
__global__ __launch_bounds__(256, 2)
void wino_gemm() {
    extern __shared__ __align__(128) char sm[];

    const int z  = blockIdx.z;
    const int o0 = blockIdx.y * 128;
    const int n0 = blockIdx.x * 128;
    const int tid = threadIdx.x;
    const int wid = tid >> 5;
    const int lane = tid & 31;
    const int warp_m = wid & 3;
    const int warp_n = wid >> 2;

    const uint32_t sbase = s2u(sm);

    const bool isA = (tid < 128);
    const int r = tid & 127;
    uint32_t dsw[8];
#pragma unroll
    for (int cc = 0; cc < 8; ++cc)
        dsw[cc] = (uint32_t)((isA ? 0 : TILEB) + r * 128 + ((cc ^ (r & 7)) << 4));

    const __half* aRow = g_U + (size_t)z * COUT * CIN + (size_t)(o0 + r) * CIN;
    const __half* bRow = g_V + (size_t)z * NT * CIN + (size_t)(n0 + r) * CIN;

    uint32_t offA0[2], offB0[4];
#pragma unroll
    for (int mt = 0; mt < 2; ++mt) {
        const int row = warp_m * 32 + mt * 16 + (lane & 15);
        offA0[mt] = (uint32_t)(row * 128 + (((lane >> 4) ^ (row & 7)) << 4));
    }
#pragma unroll
    for (int q = 0; q < 4; ++q) {
        const int n = warp_n * 64 + q * 16 + (lane & 7) + ((lane >> 4) << 3);
        offB0[q] = (uint32_t)(n * 128 + ((((lane >> 3) & 1) ^ (n & 7)) << 4));
    }

    float acc[2][8][4];
#pragma unroll
    for (int mt = 0; mt < 2; ++mt)
#pragma unroll
        for (int nt = 0; nt < 8; ++nt)
#pragma unroll
            for (int e = 0; e < 4; ++e) acc[mt][nt][e] = 0.f;

    auto issue = [&](int c) {
        const int s = c % NSTAGE;
        const uint32_t base = sbase + (uint32_t)(s * STAGEB);
        const __half* src = (isA ? aRow : bRow) + c * KC;
        if (isA) {
#pragma unroll
            for (int cc = 0; cc < 8; ++cc) cp_ca16(base + dsw[cc], src + cc * 8);
        } else {
#pragma unroll
            for (int cc = 0; cc < 8; ++cc) cp_cg16(base + dsw[cc], src + cc * 8);
        }
        cp_commit();
    };

    issue(0);
    issue(1);

    for (int c = 0; c < NCH; ++c) {
        cp_wait1();
        __syncthreads();
        if (c + 2 < NCH) issue(c + 2);
        else cp_commit();

        const uint32_t base = sbase + (uint32_t)((c % NSTAGE) * STAGEB);
        const uint32_t bA = base;
        const uint32_t bB = base + TILEB;

#pragma unroll
        for (int j = 0; j < 4; ++j) {
            const uint32_t jx = (uint32_t)(j << 5);
            uint32_t ah[2][4], bh[4][4];
#pragma unroll
            for (int mt = 0; mt < 2; ++mt) ldsm4(ah[mt], bA + (offA0[mt] ^ jx));
#pragma unroll
            for (int q = 0; q < 4; ++q)   ldsm4(bh[q], bB + (offB0[q] ^ jx));
#pragma unroll
            for (int mt = 0; mt < 2; ++mt)
#pragma unroll
                for (int nt = 0; nt < 8; ++nt) {
                    const int q = nt >> 1;
                    const int e = (nt & 1) * 2;
                    MMA(acc[mt][nt], ah[mt], bh[q][e], bh[q][e + 1]);
                }
        }
    }

    // epilogue: raw fp32 store to g_M[z][o][n]
    float* Mb = g_M + (size_t)z * COUT * NT;
#pragma unroll
    for (int mt = 0; mt < 2; ++mt) {
        const int ob = o0 + warp_m * 32 + mt * 16 + (lane >> 2);
        float* row0 = Mb + (size_t)ob * NT + n0 + warp_n * 64;
        float* row1 = row0 + (size_t)8 * NT;
#pragma unroll
        for (int nt = 0; nt < 8; ++nt) {
            const int w = nt * 8 + (lane & 3) * 2;
            *(float2*)(row0 + w) = make_float2(acc[mt][nt][0], acc[mt][nt][1]);
            *(float2*)(row1 + w) = make_float2(acc[mt][nt][2], acc[mt][nt][3]);
        }
    }
}

// ---------------------------------------------------------------------------
// Output transform: Y = A^T M A, then demod/bias/noise, write NCHW.
// grid (COUT, NB), 256 threads.
__global__ __launch_bounds__(256) void out_tf(const float* __restrict__ noise,
                                              const float* __restrict__ bias,
                                              const float* __restrict__ noise_scale,
                                              float* __restrict__ out) {
    __shared__ float plane[4096];
    const int o = blockIdx.x;
    const int b = blockIdx.y;
    const int tid = threadIdx.x;

    const size_t mi0 = (size_t)o * NT + (size_t)b * 1024;
#pragma unroll
    for (int q = 0; q < 4; ++q) {
        const int tile = q * 256 + tid;
        float m[16];
#pragma unroll
        for (int c = 0; c < 16; ++c)
            m[c] = g_M[(size_t)c * COUT * NT + mi0 + tile];
        float t0[4], t1[4];
#pragma unroll
        for (int c = 0; c < 4; ++c) {
            t0[c] = m[0 + c] + m[4 + c] + m[8 + c];
            t1[c] = m[4 + c] - m[8 + c] - m[12 + c];
        }
        const float y00 = t0[0] + t0[1] + t0[2];
        const float y01 = t0[1] - t0[2] - t0[3];
        const float y10 = t1[0] + t1[1] + t1[2];
        const float y11 = t1[1] - t1[2] - t1[3];
        const int tyy = tile >> 5;
        const int txx = tile & 31;
        plane[(2 * tyy) * 64 + 2 * txx]     = y00;
        plane[(2 * tyy) * 64 + 2 * txx + 1] = y01;
        plane[(2 * tyy + 1) * 64 + 2 * txx]     = y10;
        plane[(2 * tyy + 1) * 64 + 2 * txx + 1] = y11;
    }
    __syncthreads();

    const float dd = g_d[b * COUT + o];
    const float bb = bias[o];
    const float ns = noise_scale[0];
    const float4* nz4 = (const float4*)(noise + (size_t)b * 4096);
    float4* out4 = (float4*)(out + ((size_t)(b * COUT + o)) * 4096);
#pragma unroll
    for (int k = 0; k < 4; ++k) {
        const int f4 = k * 256 + tid;
        const float4 v = ((const float4*)plane)[f4];
        const float4 nz = nz4[f4];
        float4 res;
        res.x = v.x * dd + nz.x * ns + bb;
        res.y = v.y * dd + nz.y * ns + bb;
        res.z = v.z * dd + nz.z * ns + bb;
        res.w = v.w * dd + nz.w * ns + bb;
        out4[f4] = res;
    }
}

// ---------------------------------------------------------------------------
extern "C" void kernel_launch(void* const* d_in, const int* in_sizes, int n_in,
                              void* d_out, int out_size) {
    const float* x           = (const float*)d_in[0];
    const float* y           = (const float*)d_in[1];
    const float* noise       = (const float*)d_in[2];
    const float* weight      = (const float*)d_in[3];
    const float* bias        = (const float*)d_in[4];
    const float* mod_w       = (const float*)d_in[5];
    const float* mod_b       = (const float*)d_in[6];
    const float* noise_scale = (const float*)d_in[7];
    float* out = (float*)d_out;

    cudaFuncSetAttribute(wino_gemm, cudaFuncAttributeMaxDynamicSharedMemorySize, DYN_GEMM);
    cudaFuncSetAttribute(in_tf, cudaFuncAttributeMaxDynamicSharedMemorySize, DYN_INTF);

    prep_s<<<NB, CIN>>>(y, mod_w, mod_b);
    prep_U<<<COUT, CIN>>>(weight);
    prep_d<<<NB, COUT>>>();
    in_tf<<<dim3(32, 16, NB), 256, DYN_INTF>>>(x);
    wino_gemm<<<dim3(NT / 128, COUT / 128, 16), 256, DYN_GEMM>>>();
    out_tf<<<dim3(COUT, NB), 256>>>(noise, bias, noise_scale, out);
}

// round 7
// speedup vs baseline: 9.4253x; 1.0664x over previous
#include <cuda_runtime.h>
#include <cuda_fp16.h>
#include <cstdint>

#define NB   16
#define CIN  512
#define COUT 512
#define HID  512
#define HH   64
#define WW   64
#define NT   16384                 // 16 batches x 32x32 output tiles

// GEMM tiling (per Winograd coordinate): M=COUT, N=NT, K=CIN
#define KC     64
#define NCH    (CIN / KC)          // 8
#define TILEB  (128 * KC * 2)      // 16384 B
#define STAGEB (2 * TILEB)
#define NSTAGE 3
#define DYN_GEMM (NSTAGE * STAGEB) // 96 KB
#define DYN_INTF (36864 + 40960)   // xs plane (32x4x72 f32) + stage (16x32x40 f16)

// ---------------- static device scratch -------------------------------------
__device__ float g_s[NB * CIN];
__device__ float g_d[NB * COUT];
__device__ float g_w2[CIN * COUT];
__device__ __half g_U[(size_t)16 * COUT * CIN];   // [coord][o][i]
__device__ __half g_V[(size_t)16 * NT * CIN];     // [coord][tile][i]
__device__ __half g_M[(size_t)16 * COUT * NT];    // [coord][o][tile], fp16

// ---------------- helpers ----------------------------------------------------
__device__ __forceinline__ uint32_t s2u(const void* p) {
    uint32_t a;
    asm("{ .reg .u64 t; cvta.to.shared.u64 t, %1; cvt.u32.u64 %0, t; }" : "=r"(a) : "l"(p));
    return a;
}
__device__ __forceinline__ void cp_ca16(uint32_t dst, const void* src) {
    asm volatile("cp.async.ca.shared.global [%0], [%1], 16;"
                 :: "r"(dst), "l"(src) : "memory");
}
__device__ __forceinline__ void cp_cg16(uint32_t dst, const void* src) {
    asm volatile("cp.async.cg.shared.global [%0], [%1], 16;"
                 :: "r"(dst), "l"(src) : "memory");
}
__device__ __forceinline__ void cp_commit() {
    asm volatile("cp.async.commit_group;" ::: "memory");
}
__device__ __forceinline__ void cp_wait1() {
    asm volatile("cp.async.wait_group 1;" ::: "memory");
}
__device__ __forceinline__ void cp_wait0() {
    asm volatile("cp.async.wait_group 0;" ::: "memory");
}
__device__ __forceinline__ void ldsm4(uint32_t* r, uint32_t addr) {
    asm volatile("ldmatrix.sync.aligned.m8n8.x4.shared.b16 {%0,%1,%2,%3}, [%4];"
                 : "=r"(r[0]), "=r"(r[1]), "=r"(r[2]), "=r"(r[3]) : "r"(addr));
}
#define MMA(c, a, B0, B1) \
    asm volatile("mma.sync.aligned.m16n8k16.row.col.f32.f16.f16.f32 " \
                 "{%0,%1,%2,%3},{%4,%5,%6,%7},{%8,%9},{%0,%1,%2,%3};" \
                 : "+f"((c)[0]), "+f"((c)[1]), "+f"((c)[2]), "+f"((c)[3]) \
                 : "r"((a)[0]), "r"((a)[1]), "r"((a)[2]), "r"((a)[3]), \
                   "r"(B0), "r"(B1))

// ---------------------------------------------------------------------------
// Prep 1: style s[b,i]
__global__ void prep_s(const float* __restrict__ y,
                       const float* __restrict__ mod_w,
                       const float* __restrict__ mod_b) {
    const int b = blockIdx.x;
    const int i = threadIdx.x;
    const float ms = rsqrtf((float)HID);
    const float4* yr = (const float4*)(y + (size_t)b * HID);
    const float4* wr = (const float4*)(mod_w + (size_t)i * HID);
    float acc = 0.f;
#pragma unroll 8
    for (int h = 0; h < HID / 4; ++h) {
        float4 a = yr[h];
        float4 w = wr[h];
        acc += a.x * w.x + a.y * w.y + a.z * w.z + a.w * w.w;
    }
    g_s[b * CIN + i] = acc * ms + mod_b[i] + 1.0f;
}

// ---------------------------------------------------------------------------
// Prep 2: Winograd weight transform U = G g G^T (fp32, round once to fp16)
__global__ void prep_U(const float* __restrict__ weight) {
    const int o = blockIdx.x;
    const int i = threadIdx.x;
    const float coef = rsqrtf((float)(CIN * 9));
    const float* wp = weight + ((size_t)o * CIN + i) * 9;
    float g[3][3];
    float ss = 0.f;
#pragma unroll
    for (int r = 0; r < 3; ++r)
#pragma unroll
        for (int c = 0; c < 3; ++c) {
            const float v = wp[r * 3 + c] * coef;
            g[r][c] = v;
            ss += v * v;
        }
    g_w2[i * COUT + o] = ss;

    float T[4][3];
#pragma unroll
    for (int c = 0; c < 3; ++c) {
        T[0][c] = g[0][c];
        T[1][c] = 0.5f * (g[0][c] + g[1][c] + g[2][c]);
        T[2][c] = 0.5f * (g[0][c] - g[1][c] + g[2][c]);
        T[3][c] = g[2][c];
    }
    const size_t base = (size_t)o * CIN + i;
#pragma unroll
    for (int r = 0; r < 4; ++r) {
        float u0 = T[r][0];
        float u1 = 0.5f * (T[r][0] + T[r][1] + T[r][2]);
        float u2 = 0.5f * (T[r][0] - T[r][1] + T[r][2]);
        float u3 = T[r][2];
        g_U[(size_t)(r * 4 + 0) * COUT * CIN + base] = __float2half(u0);
        g_U[(size_t)(r * 4 + 1) * COUT * CIN + base] = __float2half(u1);
        g_U[(size_t)(r * 4 + 2) * COUT * CIN + base] = __float2half(u2);
        g_U[(size_t)(r * 4 + 3) * COUT * CIN + base] = __float2half(u3);
    }
}

// ---------------------------------------------------------------------------
// Prep 3: demod d[b,o]
__global__ void prep_d() {
    const int b = blockIdx.x;
    const int o = threadIdx.x;
    __shared__ float s2[CIN];
    for (int i = threadIdx.x; i < CIN; i += blockDim.x) {
        const float s = g_s[b * CIN + i];
        s2[i] = s * s;
    }
    __syncthreads();
    float acc = 0.f;
#pragma unroll 8
    for (int i = 0; i < CIN; ++i)
        acc += g_w2[i * COUT + o] * s2[i];
    g_d[b * COUT + o] = rsqrtf(acc + 1e-8f);
}

// ---------------------------------------------------------------------------
// Input transform: V[coord][b*1024 + ty*32 + tx][i] = B^T (x) B * s, fp16.
// Phase 1 is pure cp.async (raw x rows -> padded smem plane), style scale
// applied during the register-resident transform.
// grid (32 ty, 16 ic, 16 b), 256 threads.
#define XS_STRIDE 72                       // floats per row: [3 pad][w=-1][64][w=64][3 pad]
__global__ __launch_bounds__(256) void in_tf(const float* __restrict__ x) {
    extern __shared__ __align__(16) char smraw[];
    float* xs = (float*)smraw;                       // [32 i][4 r][72]
    __half* stage = (__half*)(smraw + 36864);        // [16 c][32 tx][40 pad]

    const int ty = blockIdx.x;
    const int ic = blockIdx.y;
    const int b  = blockIdx.z;
    const int i0 = ic * 32;
    const int tid = threadIdx.x;
    const int lane = tid & 31;
    const int wid = tid >> 5;

    // zero the whole plane (covers halo cols and out-of-image rows)
    {
        uint4* z4 = (uint4*)xs;
#pragma unroll
        for (int k = 0; k < 9; ++k)
            z4[tid + 256 * k] = make_uint4(0, 0, 0, 0);
    }
    __syncthreads();

    // async fill: interior 64 floats of each (i_l, r) row at slot 4 (16B aligned)
    const int r0 = 2 * ty - 1;
    const uint32_t xs_u = s2u(xs);
#pragma unroll
    for (int k = 0; k < 8; ++k) {
        const int idx = tid + 256 * k;      // (i_l, r, seg)
        const int i_l = idx >> 6;
        const int r = (idx >> 4) & 3;
        const int seg = idx & 15;
        const int row = r0 + r;
        if ((unsigned)row < HH) {
            const float* src = x + (((size_t)(b * CIN + i0 + i_l)) * HH + row) * WW + seg * 4;
            cp_cg16(xs_u + (uint32_t)(((i_l * 4 + r) * XS_STRIDE + 4 + seg * 4) * 4), src);
        }
    }
    cp_commit();
    cp_wait0();
    __syncthreads();

    // transform: thread (i_l = wid+8q, tx = lane) does 4x4 -> 4x4, scaled by s
#pragma unroll
    for (int q = 0; q < 4; ++q) {
        const int i_l = wid + 8 * q;
        const int tx = lane;
        const float sc = g_s[b * CIN + i0 + i_l];
        const float* base = &xs[(i_l * 4) * XS_STRIDE + 3 + 2 * tx];
        float d[4][4];
#pragma unroll
        for (int r = 0; r < 4; ++r)
#pragma unroll
            for (int c = 0; c < 4; ++c)
                d[r][c] = base[r * XS_STRIDE + c] * sc;
        float t[4][4];
#pragma unroll
        for (int c = 0; c < 4; ++c) {
            t[0][c] = d[0][c] - d[2][c];
            t[1][c] = d[1][c] + d[2][c];
            t[2][c] = d[2][c] - d[1][c];
            t[3][c] = d[1][c] - d[3][c];
        }
#pragma unroll
        for (int r = 0; r < 4; ++r) {
            const float v0 = t[r][0] - t[r][2];
            const float v1 = t[r][1] + t[r][2];
            const float v2 = t[r][2] - t[r][1];
            const float v3 = t[r][1] - t[r][3];
            stage[((r * 4 + 0) * 32 + tx) * 40 + i_l] = __float2half(v0);
            stage[((r * 4 + 1) * 32 + tx) * 40 + i_l] = __float2half(v1);
            stage[((r * 4 + 2) * 32 + tx) * 40 + i_l] = __float2half(v2);
            stage[((r * 4 + 3) * 32 + tx) * 40 + i_l] = __float2half(v3);
        }
    }
    __syncthreads();

    // coalesced copy stage -> g_V
    const size_t nbase = (size_t)b * 1024 + ty * 32;
#pragma unroll
    for (int k = 0; k < 2; ++k) {
        const int p = tid + 256 * k;
        const int c16 = p >> 5;
        const int tx = p & 31;
        const uint4* src = (const uint4*)&stage[((size_t)c16 * 32 + tx) * 40];
        uint4* dst = (uint4*)(g_V + ((size_t)c16 * NT + nbase + tx) * CIN + i0);
        dst[0] = src[0]; dst[1] = src[1]; dst[2] = src[2]; dst[3] = src[3];
    }
}

// ---------------------------------------------------------------------------
// Winograd GEMM: per coord z, M[o, tile] = sum_i U[z][o][i] V[z][tile][i].
// CTA 128x128, 8 warps (4x2), warp 32x64, fp16 HMMA, 3-stage cp.async.
// Epilogue stores fp16 M.
__global__ __launch_bounds__(256, 2)
void wino_gemm() {
    extern __shared__ __align__(128) char sm[];

    const int z  = blockIdx.z;
    const int o0 = blockIdx.y * 128;
    const int n0 = blockIdx.x * 128;
    const int tid = threadIdx.x;
    const int wid = tid >> 5;
    const int lane = tid & 31;
    const int warp_m = wid & 3;
    const int warp_n = wid >> 2;

    const uint32_t sbase = s2u(sm);

    const bool isA = (tid < 128);
    const int r = tid & 127;
    uint32_t dsw[8];
#pragma unroll
    for (int cc = 0; cc < 8; ++cc)
        dsw[cc] = (uint32_t)((isA ? 0 : TILEB) + r * 128 + ((cc ^ (r & 7)) << 4));

    const __half* aRow = g_U + (size_t)z * COUT * CIN + (size_t)(o0 + r) * CIN;
    const __half* bRow = g_V + (size_t)z * NT * CIN + (size_t)(n0 + r) * CIN;

    uint32_t offA0[2], offB0[4];
#pragma unroll
    for (int mt = 0; mt < 2; ++mt) {
        const int row = warp_m * 32 + mt * 16 + (lane & 15);
        offA0[mt] = (uint32_t)(row * 128 + (((lane >> 4) ^ (row & 7)) << 4));
    }
#pragma unroll
    for (int q = 0; q < 4; ++q) {
        const int n = warp_n * 64 + q * 16 + (lane & 7) + ((lane >> 4) << 3);
        offB0[q] = (uint32_t)(n * 128 + ((((lane >> 3) & 1) ^ (n & 7)) << 4));
    }

    float acc[2][8][4];
#pragma unroll
    for (int mt = 0; mt < 2; ++mt)
#pragma unroll
        for (int nt = 0; nt < 8; ++nt)
#pragma unroll
            for (int e = 0; e < 4; ++e) acc[mt][nt][e] = 0.f;

    auto issue = [&](int c) {
        const int s = c % NSTAGE;
        const uint32_t base = sbase + (uint32_t)(s * STAGEB);
        const __half* src = (isA ? aRow : bRow) + c * KC;
        if (isA) {
#pragma unroll
            for (int cc = 0; cc < 8; ++cc) cp_ca16(base + dsw[cc], src + cc * 8);
        } else {
#pragma unroll
            for (int cc = 0; cc < 8; ++cc) cp_cg16(base + dsw[cc], src + cc * 8);
        }
        cp_commit();
    };

    issue(0);
    issue(1);

    for (int c = 0; c < NCH; ++c) {
        cp_wait1();
        __syncthreads();
        if (c + 2 < NCH) issue(c + 2);
        else cp_commit();

        const uint32_t base = sbase + (uint32_t)((c % NSTAGE) * STAGEB);
        const uint32_t bA = base;
        const uint32_t bB = base + TILEB;

#pragma unroll
        for (int j = 0; j < 4; ++j) {
            const uint32_t jx = (uint32_t)(j << 5);
            uint32_t ah[2][4], bh[4][4];
#pragma unroll
            for (int mt = 0; mt < 2; ++mt) ldsm4(ah[mt], bA + (offA0[mt] ^ jx));
#pragma unroll
            for (int q = 0; q < 4; ++q)   ldsm4(bh[q], bB + (offB0[q] ^ jx));
#pragma unroll
            for (int mt = 0; mt < 2; ++mt)
#pragma unroll
                for (int nt = 0; nt < 8; ++nt) {
                    const int q = nt >> 1;
                    const int e = (nt & 1) * 2;
                    MMA(acc[mt][nt], ah[mt], bh[q][e], bh[q][e + 1]);
                }
        }
    }

    // epilogue: fp16 store to g_M[z][o][n]
    __half* Mb = g_M + (size_t)z * COUT * NT;
#pragma unroll
    for (int mt = 0; mt < 2; ++mt) {
        const int ob = o0 + warp_m * 32 + mt * 16 + (lane >> 2);
        __half* row0 = Mb + (size_t)ob * NT + n0 + warp_n * 64;
        __half* row1 = row0 + (size_t)8 * NT;
#pragma unroll
        for (int nt = 0; nt < 8; ++nt) {
            const int w = nt * 8 + (lane & 3) * 2;
            *(__half2*)(row0 + w) = __floats2half2_rn(acc[mt][nt][0], acc[mt][nt][1]);
            *(__half2*)(row1 + w) = __floats2half2_rn(acc[mt][nt][2], acc[mt][nt][3]);
        }
    }
}

// ---------------------------------------------------------------------------
// Output transform: Y = A^T M A, then demod/bias/noise, write NCHW.
__global__ __launch_bounds__(256) void out_tf(const float* __restrict__ noise,
                                              const float* __restrict__ bias,
                                              const float* __restrict__ noise_scale,
                                              float* __restrict__ out) {
    __shared__ float plane[4096];
    const int o = blockIdx.x;
    const int b = blockIdx.y;
    const int tid = threadIdx.x;

    const size_t mi0 = (size_t)o * NT + (size_t)b * 1024;
#pragma unroll
    for (int q = 0; q < 4; ++q) {
        const int tile = q * 256 + tid;
        float m[16];
#pragma unroll
        for (int c = 0; c < 16; ++c)
            m[c] = __half2float(g_M[(size_t)c * COUT * NT + mi0 + tile]);
        float t0[4], t1[4];
#pragma unroll
        for (int c = 0; c < 4; ++c) {
            t0[c] = m[0 + c] + m[4 + c] + m[8 + c];
            t1[c] = m[4 + c] - m[8 + c] - m[12 + c];
        }
        const float y00 = t0[0] + t0[1] + t0[2];
        const float y01 = t0[1] - t0[2] - t0[3];
        const float y10 = t1[0] + t1[1] + t1[2];
        const float y11 = t1[1] - t1[2] - t1[3];
        const int tyy = tile >> 5;
        const int txx = tile & 31;
        plane[(2 * tyy) * 64 + 2 * txx]     = y00;
        plane[(2 * tyy) * 64 + 2 * txx + 1] = y01;
        plane[(2 * tyy + 1) * 64 + 2 * txx]     = y10;
        plane[(2 * tyy + 1) * 64 + 2 * txx + 1] = y11;
    }
    __syncthreads();

    const float dd = g_d[b * COUT + o];
    const float bb = bias[o];
    const float ns = noise_scale[0];
    const float4* nz4 = (const float4*)(noise + (size_t)b * 4096);
    float4* out4 = (float4*)(out + ((size_t)(b * COUT + o)) * 4096);
#pragma unroll
    for (int k = 0; k < 4; ++k) {
        const int f4 = k * 256 + tid;
        const float4 v = ((const float4*)plane)[f4];
        const float4 nz = nz4[f4];
        float4 res;
        res.x = v.x * dd + nz.x * ns + bb;
        res.y = v.y * dd + nz.y * ns + bb;
        res.z = v.z * dd + nz.z * ns + bb;
        res.w = v.w * dd + nz.w * ns + bb;
        out4[f4] = res;
    }
}

// ---------------------------------------------------------------------------
extern "C" void kernel_launch(void* const* d_in, const int* in_sizes, int n_in,
                              void* d_out, int out_size) {
    const float* x           = (const float*)d_in[0];
    const float* y           = (const float*)d_in[1];
    const float* noise       = (const float*)d_in[2];
    const float* weight      = (const float*)d_in[3];
    const float* bias        = (const float*)d_in[4];
    const float* mod_w       = (const float*)d_in[5];
    const float* mod_b       = (const float*)d_in[6];
    const float* noise_scale = (const float*)d_in[7];
    float* out = (float*)d_out;

    cudaFuncSetAttribute(wino_gemm, cudaFuncAttributeMaxDynamicSharedMemorySize, DYN_GEMM);
    cudaFuncSetAttribute(in_tf, cudaFuncAttributeMaxDynamicSharedMemorySize, DYN_INTF);

    prep_s<<<NB, CIN>>>(y, mod_w, mod_b);
    prep_U<<<COUT, CIN>>>(weight);
    prep_d<<<NB, COUT>>>();
    in_tf<<<dim3(32, 16, NB), 256, DYN_INTF>>>(x);
    wino_gemm<<<dim3(NT / 128, COUT / 128, 16), 256, DYN_GEMM>>>();
    out_tf<<<dim3(COUT, NB), 256>>>(noise, bias, noise_scale, out);
}